// round 17
// baseline (speedup 1.0000x reference)
#include <cuda_runtime.h>

#define NA_MAX 200000
#define NA_PAD 200704          // NA_MAX padded to 16B multiple for int4 copies
#define COULOMB 14.399645478425668f
#define PEXP 0.23f
#define A0C 0.4685f

// -d_k * log2(e): phi terms become exp2f(s * K) = FMA + EX2
#define K0 (-0.29087618f)
#define K1 (-0.58126163f)
#define K2 (-1.35943713f)
#define K3 (-4.61633539f)

__device__ unsigned char g_type_u8[NA_PAD];
__device__ float4 g_pair0[16];   // (rc, 1/a, factor/2, C/2)
__device__ float2 g_pair1[16];   // (A/6, B/8)
__device__ float  g_rcmax;

// ---------------- prep: u8 type copy + slim pair tables ----------------
__global__ void prep_pack(const float* __restrict__ cov, const float* __restrict__ anum,
                          const int* __restrict__ types, int n_atoms) {
    int gi = blockIdx.x * blockDim.x + threadIdx.x;
    if (gi < NA_PAD) g_type_u8[gi] = (gi < n_atoms) ? (unsigned char)types[gi] : 0;

    if (blockIdx.x == 0 && threadIdx.x < 16) {
        int t = threadIdx.x;
        int ti = t >> 2, tj = t & 3;
        float zi = anum[ti], zj = anum[tj];
        float rc = cov[ti] + cov[tj];
        float inv_a = (powf(zi, PEXP) + powf(zj, PEXP)) / A0C;
        const float cc[4] = {0.02817f, 0.28022f, 0.50986f, 0.18175f};
        const float dd[4] = {0.20162f, 0.4029f, 0.94229f, 3.1998f};
        float da[4];
        #pragma unroll
        for (int k = 0; k < 4; k++) da[k] = dd[k] * inv_a;
        float factor = COULOMB * zi * zj;

        float phi = 0.f, dphi = 0.f, d2phi = 0.f;
        #pragma unroll
        for (int k = 0; k < 4; k++) {
            float ex = expf(-rc * da[k]);
            phi   += cc[k] * ex;
            dphi  += -cc[k] * da[k] * ex;
            d2phi += cc[k] * da[k] * da[k] * ex;
        }
        float inv_rc = 1.0f / rc;
        float ec   = factor * inv_rc * phi;
        float dec  = factor * inv_rc * (-phi * inv_rc + dphi);
        float d2ec = factor * inv_rc * (d2phi - 2.0f * inv_rc * dphi + 2.0f * phi * inv_rc * inv_rc);

        float A = (-3.0f * dec + rc * d2ec) * inv_rc * inv_rc;
        float B = ( 2.0f * dec - rc * d2ec) * inv_rc * inv_rc * inv_rc;
        float C = -ec + rc * dec * 0.5f - rc * rc * d2ec * (1.0f / 12.0f);

        g_pair0[t] = make_float4(rc, inv_a, factor * 0.5f, C * 0.5f);
        g_pair1[t] = make_float2(A * (1.0f / 6.0f), B * 0.125f);

        float m = rc;
        #pragma unroll
        for (int o = 8; o > 0; o >>= 1)
            m = fmaxf(m, __shfl_xor_sync(0xFFFF, m, o));
        if (t == 0) g_rcmax = m;
    }
}

// ---------------- main edge kernel: u8 SMEM table + software-pipelined streaming ----------------
__global__ void __launch_bounds__(1024, 1)
zbl_edges(const float4* __restrict__ rij4, const int4* __restrict__ fa4,
          const int4* __restrict__ sa4, float* __restrict__ out, int nquads) {
    extern __shared__ unsigned char smem_raw[];
    unsigned char* s_types = smem_raw;                       // NA_PAD bytes
    __shared__ float4 s_p0[16];
    __shared__ float2 s_p1[16];

    {
        int4* dst = (int4*)s_types;
        const int4* src = (const int4*)g_type_u8;
        for (int j = threadIdx.x; j < NA_PAD / 16; j += 1024) dst[j] = src[j];
        if (threadIdx.x < 16) {
            s_p0[threadIdx.x] = g_pair0[threadIdx.x];
            s_p1[threadIdx.x] = g_pair1[threadIdx.x];
        }
    }
    __syncthreads();
    const float rcmax = g_rcmax;

    const int stride = gridDim.x * blockDim.x;
    int i = blockIdx.x * blockDim.x + threadIdx.x;

    float4 r4; int4 f4, s4;
    if (i < nquads) {
        r4 = __ldcs(rij4 + i);
        f4 = __ldcs(fa4 + i);
        s4 = __ldcs(sa4 + i);
    }

    while (i < nquads) {
        int inext = i + stride;
        // prefetch next iteration's streaming data before touching this quad
        float4 nr; int4 nf, ns;
        if (inext < nquads) {
            nr = __ldcs(rij4 + inext);
            nf = __ldcs(fa4 + inext);
            ns = __ldcs(sa4 + inext);
        }

        const float* rr = &r4.x;
        const int*   ff = &f4.x;
        const int*   ss = &s4.x;
        #pragma unroll
        for (int k = 0; k < 4; k++) {
            float r = rr[k];
            if (r > rcmax) continue;               // ~29%: zero table traffic
            int fa = ff[k];
            int p  = ((int)s_types[fa] << 2) | (int)s_types[ss[k]];
            float4 t0 = s_p0[p];                   // rc, 1/a, factor/2, C/2
            if (r <= t0.x) {
                float2 t1 = s_p1[p];               // A/6, B/8
                float s = r * t0.y;
                float e0 = exp2f(s * K0);
                float e1 = exp2f(s * K1);
                float e2 = exp2f(s * K2);
                float e3 = exp2f(s * K3);
                float phi = 0.02817f * e0 + 0.28022f * e1 + 0.50986f * e2 + 0.18175f * e3;
                float e = t0.z * __fdividef(phi, r) + (t1.x + t1.y * r) * r * r * r + t0.w;
                atomicAdd(out + fa, e);
            }
        }

        r4 = nr; f4 = nf; s4 = ns;
        i = inext;
    }
}

// scalar tail (global tables; E % 4 != 0 safety)
__global__ void zbl_tail(const float* __restrict__ rij, const int* __restrict__ fst,
                         const int* __restrict__ snd, float* __restrict__ out,
                         int start, int nedges) {
    int i = start + blockIdx.x * blockDim.x + threadIdx.x;
    if (i >= nedges) return;
    float r  = rij[i];
    int   fa = fst[i];
    int p = ((int)g_type_u8[fa] << 2) | (int)g_type_u8[snd[i]];
    float4 t0 = g_pair0[p];
    if (r <= t0.x) {
        float2 t1 = g_pair1[p];
        float s = r * t0.y;
        float e0 = exp2f(s * K0);
        float e1 = exp2f(s * K1);
        float e2 = exp2f(s * K2);
        float e3 = exp2f(s * K3);
        float phi = 0.02817f * e0 + 0.28022f * e1 + 0.50986f * e2 + 0.18175f * e3;
        float e = t0.z * __fdividef(phi, r) + (t1.x + t1.y * r) * r * r * r + t0.w;
        atomicAdd(out + fa, e);
    }
}

extern "C" void kernel_launch(void* const* d_in, const int* in_sizes, int n_in,
                              void* d_out, int out_size) {
    const float* rij  = (const float*)d_in[0];
    const float* cov  = (const float*)d_in[1];
    const float* anum = (const float*)d_in[2];
    const int*   fst  = (const int*)d_in[3];
    const int*   snd  = (const int*)d_in[4];
    const int*   typ  = (const int*)d_in[5];
    float* out = (float*)d_out;

    int n_edges = in_sizes[0];
    int n_atoms = in_sizes[5];
    if (n_atoms > NA_MAX) n_atoms = NA_MAX;

    cudaMemsetAsync(out, 0, (size_t)out_size * sizeof(float));

    prep_pack<<<(NA_PAD + 255) / 256, 256>>>(cov, anum, typ, n_atoms);

    const int SMEM_BYTES = NA_PAD;   // 200704 B dynamic -> 1 CTA/SM
    cudaFuncSetAttribute(zbl_edges, cudaFuncAttributeMaxDynamicSharedMemorySize, SMEM_BYTES);

    int nquads = n_edges / 4;
    if (nquads > 0) {
        int grid = (nquads + 1023) / 1024;
        if (grid > 148) grid = 148;   // persistent, 1 CTA/SM
        zbl_edges<<<grid, 1024, SMEM_BYTES>>>(
            (const float4*)rij, (const int4*)fst, (const int4*)snd, out, nquads);
    }
    int tail_start = nquads * 4;
    int tail = n_edges - tail_start;
    if (tail > 0) {
        zbl_tail<<<(tail + 255) / 256, 256>>>(rij, fst, snd, out, tail_start, n_edges);
    }
}